// round 9
// baseline (speedup 1.0000x reference)
#include <cuda_runtime.h>

#define BB 32
#define TT 4096
#define DD 128
#define CC 16              // timesteps per chunk
#define NCH (TT / CC)      // 256 chunks per channel

// Per-(b,chunk,d) summaries. float2 = (x, t); t < 0 => "no observation".
// After k_scan these hold the INCOMING state for each chunk with the
// reference's fallbacks already substituted (so t is always valid >= 0).
__device__ float2 g_fwd[BB * NCH * DD];            // 8 MB
__device__ float2 g_bwd[BB * NCH * DD];            // 8 MB
__device__ unsigned short g_mbits[BB * NCH * DD];  // packed mask, 2 MB

// ---------------------------------------------------------------------------
// Mask element-width autodetect. The harness converts the bool mask to one of
// its supported dtypes (f32/i32/bf16) or leaves it as 1-byte bools. Probe the
// first 64 words and classify by bit pattern. Deterministic, warp-uniform.
// ---------------------------------------------------------------------------
__device__ __forceinline__ int mask_width(const unsigned int* __restrict__ m32)
{
    int w1 = 0, w2 = 0, w4 = 0;
#pragma unroll
    for (int i = 0; i < 64; ++i) {
        const unsigned w = m32[i];
        if (w == 0u) continue;
        if (w == 0x3F800000u) { w4 = 1; continue; }          // float32 1.0
        if ((w & 0xFEFEFEFEu) == 0u) {                       // all bytes in {0,1}
            if (w > 1u) w1 = 1;                              // multiple byte lanes
            continue;                                        // w==1: ambiguous
        }
        const unsigned lo = w & 0xFFFFu, hi = w >> 16;
        if ((lo == 0u || lo == 0x3F80u) && (hi == 0u || hi == 0x3F80u))
            w2 = 1;                                          // bf16 1.0 halves
    }
    if (w1) return 1;
    if (w4) return 4;
    if (w2) return 2;
    return 4;  // int32 0/1 (all probed words were 0 or 1)
}

__device__ __forceinline__ bool mtest(const void* __restrict__ m, long idx, int width)
{
    if (width == 1) return ((const unsigned char*)m)[idx]  != 0;
    if (width == 2) return ((const unsigned short*)m)[idx] != 0;
    return ((const unsigned int*)m)[idx] != 0u;
}

// ---------------------------------------------------------------------------
// Kernel 1: per-chunk summary. Reads mask fully, gathers values/times only at
// the first/last observed slot of the chunk. grid=(NCH,BB), block=DD.
// ---------------------------------------------------------------------------
__global__ __launch_bounds__(DD)
void k_summary(const float* __restrict__ v, const float* __restrict__ tm,
               const void* __restrict__ m)
{
    const int width = mask_width((const unsigned int*)m);

    const int d  = threadIdx.x;
    const int ch = blockIdx.x;
    const int b  = blockIdx.y;
    const long base = (long)(b * TT + ch * CC) * DD + d;

    unsigned bits = 0;
#pragma unroll
    for (int i = 0; i < CC; ++i) {
        if (mtest(m, base + (long)i * DD, width)) bits |= (1u << i);
    }

    float2 f, bw;
    if (bits) {
        const int last  = 31 - __clz(bits);
        const int first = __ffs(bits) - 1;
        f.x  = v [base + (long)last  * DD];
        f.y  = tm[base + (long)last  * DD];
        bw.x = v [base + (long)first * DD];
        bw.y = tm[base + (long)first * DD];
    } else {
        f  = make_float2(0.f, -1.f);
        bw = make_float2(0.f, -1.f);
    }

    const int s = (b * NCH + ch) * DD + d;
    g_fwd[s]   = f;
    g_bwd[s]   = bw;
    g_mbits[s] = (unsigned short)bits;
}

// ---------------------------------------------------------------------------
// Kernel 2: sequential scan of chunk summaries per channel (in-place rewrite:
// summary -> incoming state for that chunk). Fallbacks baked in:
//   forward : (x=0, t=times[b,0,d])   backward: (x=0, t=times[b,T-1,d])
// grid = BB, block = DD.
// ---------------------------------------------------------------------------
__global__ __launch_bounds__(DD)
void k_scan(const float* __restrict__ tm)
{
    const int d = threadIdx.x;
    const int b = blockIdx.x;
    const int base = (b * NCH) * DD + d;

    const float t_first = tm[(long)(b * TT) * DD + d];
    const float t_last  = tm[(long)(b * TT + (TT - 1)) * DD + d];

    float2 st = make_float2(0.f, t_first);
#pragma unroll 8
    for (int ch = 0; ch < NCH; ++ch) {
        float2 s = g_fwd[base + ch * DD];
        g_fwd[base + ch * DD] = st;
        if (s.y >= 0.f) st = s;
    }

    st = make_float2(0.f, t_last);
#pragma unroll 8
    for (int ch = NCH - 1; ch >= 0; --ch) {
        float2 s = g_bwd[base + ch * DD];
        g_bwd[base + ch * DD] = st;
        if (s.y >= 0.f) st = s;
    }
}

// ---------------------------------------------------------------------------
// Kernel 3: local bidirectional fill + interpolation. Each thread owns a
// 16-timestep chunk of one channel, all state in registers.
// grid = (NCH, BB), block = DD.
// ---------------------------------------------------------------------------
__global__ __launch_bounds__(DD)
void k_interp(const float* __restrict__ v, const float* __restrict__ tm,
              float* __restrict__ out)
{
    const int d  = threadIdx.x;
    const int ch = blockIdx.x;
    const int b  = blockIdx.y;
    const long base = (long)(b * TT + ch * CC) * DD + d;
    const int  s    = (b * NCH + ch) * DD + d;

    float vv[CC], tt[CC];
#pragma unroll
    for (int i = 0; i < CC; ++i) {
        vv[i] = v [base + (long)i * DD];
        tt[i] = tm[base + (long)i * DD];
    }
    const unsigned bits = g_mbits[s];
    float2 fst = g_fwd[s];   // incoming (x_last, t_last), fallback-baked
    float2 bst = g_bwd[s];   // incoming (x_next, t_next), fallback-baked

    // backward local scan: inclusive next-observed per slot
    float xn[CC], tn[CC];
#pragma unroll
    for (int i = CC - 1; i >= 0; --i) {
        if (bits & (1u << i)) { bst.x = vv[i]; bst.y = tt[i]; }
        xn[i] = bst.x;
        tn[i] = bst.y;
    }

    // forward local scan + interpolate + store
#pragma unroll
    for (int i = 0; i < CC; ++i) {
        const bool mi = (bits >> i) & 1u;
        if (mi) { fst.x = vv[i]; fst.y = tt[i]; }
        const float denom = tn[i] - fst.y;
        const float num   = fst.x * (tn[i] - tt[i]) + xn[i] * (tt[i] - fst.y);
        const float itp   = (denom != 0.f) ? (num / denom) : 0.f;
        out[base + (long)i * DD] = mi ? vv[i] : itp;
    }
}

// ---------------------------------------------------------------------------
extern "C" void kernel_launch(void* const* d_in, const int* in_sizes, int n_in,
                              void* d_out, int out_size)
{
    const float* v   = (const float*)d_in[0];
    const float* tm  = (const float*)d_in[1];
    const void*  m   = (const void*)d_in[2];
    float*       out = (float*)d_out;

    dim3 grid(NCH, BB);
    k_summary<<<grid, DD>>>(v, tm, m);
    k_scan<<<BB, DD>>>(tm);
    k_interp<<<grid, DD>>>(v, tm, out);
}